// round 6
// baseline (speedup 1.0000x reference)
#include <cuda_runtime.h>
#include <cuda_fp16.h>
#include <cstdint>

#define TGT 1024
#define SRC 1024
#define BSZb 4
#define EMB 1024
#define NH 16
#define HD 64

// -------- device scratch (allocation-free rule: __device__ globals) --------
__device__ __half g_q[BSZb * NH * TGT * HD];        // (b,h,t,d) scaled, fp16
__device__ __half g_k[BSZb * NH * SRC * HD];        // (b,h,s,d) fp16
__device__ __half g_v[BSZb * NH * SRC * HD];        // (b,h,s,d) fp16
__device__ __half g_ctx_h[TGT * BSZb * EMB];        // (t,b,e) fp16

__device__ __forceinline__ uint32_t h2u(__half2 h) {
    return *reinterpret_cast<uint32_t*>(&h);
}

__device__ __forceinline__ void mma16(float* d, uint32_t a0, uint32_t a1,
                                      uint32_t a2, uint32_t a3,
                                      uint32_t b0, uint32_t b1) {
    asm volatile(
        "mma.sync.aligned.m16n8k16.row.col.f32.f16.f16.f32 "
        "{%0,%1,%2,%3}, {%4,%5,%6,%7}, {%8,%9}, {%0,%1,%2,%3};"
        : "+f"(d[0]), "+f"(d[1]), "+f"(d[2]), "+f"(d[3])
        : "r"(a0), "r"(a1), "r"(a2), "r"(a3), "r"(b0), "r"(b1));
}

// ===========================================================================
// Fused attention: scores + softmax + mask + avg + PV, one CTA per (b, 32 t)
// ===========================================================================
// SMEM layout (bytes):
#define OFF_SC 0                      // 32 x 1024 fp32, swizzled      131072
#define OFF_Q  131072                 // 32 x 64 fp16, swizzled          4096
#define OFF_K0 135168                 // K chunk (s,d) swz / V^T (d,s)  17920
#define OFF_K1 153088
#define SMEM_FUSED 171008

// sc: fp32, row r (0..31) stride 1024 words; 16B-granule XOR (r&7)
__device__ __forceinline__ int sc_byte(int r, int w) {
    return OFF_SC + (r << 12) + ((((w >> 2) ^ (r & 7)) << 4) | ((w & 3) << 2));
}
// q/k: fp16, 64 halves (32 words) per row, 16B-granule XOR (r&7)
__device__ __forceinline__ int qk_byte(int base, int r, int ww) {
    return base + (r << 7) + ((((ww >> 2) ^ (r & 7)) << 4) | ((ww & 3) << 2));
}

__global__ void __launch_bounds__(256, 1)
fused_attn_kernel(const float* __restrict__ hard, float* __restrict__ avg_out)
{
    extern __shared__ char sm[];
    const int b = blockIdx.y;
    const int t0 = blockIdx.x * 32;
    const int tid = threadIdx.x;
    const int lane = tid & 31;
    const int w = tid >> 5;
    const int l4 = lane >> 2;        // 0..7
    const int lc = lane & 3;         // 0..3

    // softmax ownership: row srow, columns j*8+ssub
    const int srow = tid >> 3;
    const int ssub = tid & 7;

    float avg[128];
#pragma unroll
    for (int j = 0; j < 128; j++) avg[j] = 0.f;
    uint32_t mbits[4] = {0u, 0u, 0u, 0u};

#pragma unroll 1
    for (int h = 0; h < NH; h++) {
        const size_t bh = (size_t)(b * NH + h);
        const __half* qg = g_q + bh * (TGT * HD);
        const __half* kg = g_k + bh * (SRC * HD);
        const __half* vg = g_v + bh * (SRC * HD);

        __syncthreads();   // protect q/kv/sc reuse across heads

        // ---- load Q tile (32 x 64) ----
        {
            int r = tid >> 3, g = tid & 7;
            uint4 qv = *(const uint4*)(qg + (size_t)(t0 + r) * HD + g * 8);
            *(uint4*)(sm + OFF_Q + r * 128 + ((g ^ (r & 7)) << 4)) = qv;
        }

        // ---- phase A: scores = Q K^T, 8 s-chunks of 128 ----
        uint4 kf[4];
        {   // fetch+store chunk 0
#pragma unroll
            for (int it = 0; it < 4; it++) {
                int idx = tid + it * 256, r = idx >> 3, g = idx & 7;
                kf[it] = *(const uint4*)(kg + (size_t)r * HD + g * 8);
            }
#pragma unroll
            for (int it = 0; it < 4; it++) {
                int idx = tid + it * 256, r = idx >> 3, g = idx & 7;
                *(uint4*)(sm + OFF_K0 + r * 128 + ((g ^ (r & 7)) << 4)) = kf[it];
            }
        }
        __syncthreads();

#pragma unroll 1
        for (int ch = 0; ch < 8; ch++) {
            const int kb = (ch & 1) ? OFF_K1 : OFF_K0;
            if (ch < 7) {
                const __half* kgc = kg + (size_t)(ch + 1) * 128 * HD;
#pragma unroll
                for (int it = 0; it < 4; it++) {
                    int idx = tid + it * 256, r = idx >> 3, g = idx & 7;
                    kf[it] = *(const uint4*)(kgc + (size_t)r * HD + g * 8);
                }
            }

            float acc[2][2][4];
#pragma unroll
            for (int i = 0; i < 2; i++)
#pragma unroll
                for (int j = 0; j < 2; j++)
#pragma unroll
                    for (int q = 0; q < 4; q++) acc[i][j][q] = 0.f;

#pragma unroll
            for (int ks = 0; ks < 4; ks++) {
                const int ww0 = ks * 8 + lc, ww1 = ww0 + 4;
                uint32_t bfr[2][2];
#pragma unroll
                for (int nt = 0; nt < 2; nt++) {
                    int s = w * 16 + nt * 8 + l4;
                    bfr[nt][0] = *(uint32_t*)(sm + qk_byte(kb, s, ww0));
                    bfr[nt][1] = *(uint32_t*)(sm + qk_byte(kb, s, ww1));
                }
#pragma unroll
                for (int mt = 0; mt < 2; mt++) {
                    int r = mt * 16 + l4;
                    uint32_t a0 = *(uint32_t*)(sm + qk_byte(OFF_Q, r, ww0));
                    uint32_t a1 = *(uint32_t*)(sm + qk_byte(OFF_Q, r + 8, ww0));
                    uint32_t a2 = *(uint32_t*)(sm + qk_byte(OFF_Q, r, ww1));
                    uint32_t a3 = *(uint32_t*)(sm + qk_byte(OFF_Q, r + 8, ww1));
#pragma unroll
                    for (int nt = 0; nt < 2; nt++)
                        mma16(acc[mt][nt], a0, a1, a2, a3, bfr[nt][0], bfr[nt][1]);
                }
            }

            // store scores to sc
#pragma unroll
            for (int mt = 0; mt < 2; mt++) {
#pragma unroll
                for (int nt = 0; nt < 2; nt++) {
                    int rr = mt * 16 + l4;
                    int wi = ch * 128 + w * 16 + nt * 8 + 2 * lc;
                    *(float2*)(sm + sc_byte(rr, wi)) =
                        make_float2(acc[mt][nt][0], acc[mt][nt][1]);
                    *(float2*)(sm + sc_byte(rr + 8, wi)) =
                        make_float2(acc[mt][nt][2], acc[mt][nt][3]);
                }
            }

            if (ch < 7) {
                const int nb = (ch & 1) ? OFF_K0 : OFF_K1;
#pragma unroll
                for (int it = 0; it < 4; it++) {
                    int idx = tid + it * 256, r = idx >> 3, g = idx & 7;
                    *(uint4*)(sm + nb + r * 128 + ((g ^ (r & 7)) << 4)) = kf[it];
                }
            }
            __syncthreads();
        }

        // ---- softmax + mask + avg; P (fp32) left in sc ----
        {
            float m = -1e30f;
#pragma unroll
            for (int j = 0; j < 128; j++)
                m = fmaxf(m, *(float*)(sm + sc_byte(srow, j * 8 + ssub)));
#pragma unroll
            for (int o = 1; o < 8; o <<= 1)
                m = fmaxf(m, __shfl_xor_sync(0xffffffffu, m, o));

            float s = 0.f;
#pragma unroll
            for (int j = 0; j < 128; j++) {
                float* p = (float*)(sm + sc_byte(srow, j * 8 + ssub));
                float e = __expf(*p - m);
                *p = e;
                s += e;
            }
#pragma unroll
            for (int o = 1; o < 8; o <<= 1)
                s += __shfl_xor_sync(0xffffffffu, s, o);
            const float inv = 1.0f / s;

            if (h == 0) {
                const float* mrow = hard + ((size_t)b * TGT + t0 + srow) * SRC;
#pragma unroll
                for (int j = 0; j < 128; j++) {
                    uint32_t bit = (mrow[j * 8 + ssub] > 0.5f) ? 1u : 0u;
                    mbits[j >> 5] |= bit << (j & 31);
                    float* p = (float*)(sm + sc_byte(srow, j * 8 + ssub));
                    float pv = (*p) * inv * (float)bit;
                    *p = pv;
                    avg[j] += pv;
                }
            } else {
#pragma unroll
                for (int j = 0; j < 128; j++) {
                    float mk = (float)((mbits[j >> 5] >> (j & 31)) & 1u);
                    float* p = (float*)(sm + sc_byte(srow, j * 8 + ssub));
                    float pv = (*p) * inv * mk;
                    *p = pv;
                    avg[j] += pv;
                }
            }
        }
        __syncthreads();

        // ---- phase C: ctx = P V  (k = s, 8 chunks of 128) ----
        uint32_t pv0[8], pv1[8];
        {   // fetch+store V chunk 0 (transposed to (d,s), stride 69 words)
#pragma unroll
            for (int it = 0; it < 8; it++) {
                int s0 = it * 16 + (tid >> 5) * 2, dp = tid & 31;
                pv0[it] = *(const uint32_t*)(vg + (size_t)s0 * HD + dp * 2);
                pv1[it] = *(const uint32_t*)(vg + (size_t)(s0 + 1) * HD + dp * 2);
            }
#pragma unroll
            for (int it = 0; it < 8; it++) {
                int s0 = it * 16 + (tid >> 5) * 2, dp = tid & 31;
                *(uint32_t*)(sm + OFF_K0 + (2 * dp) * 276 + (s0 >> 1) * 4) =
                    __byte_perm(pv0[it], pv1[it], 0x5410);
                *(uint32_t*)(sm + OFF_K0 + (2 * dp + 1) * 276 + (s0 >> 1) * 4) =
                    __byte_perm(pv0[it], pv1[it], 0x7632);
            }
        }
        __syncthreads();

        float cacc[2][4];
#pragma unroll
        for (int nt = 0; nt < 2; nt++)
#pragma unroll
            for (int q = 0; q < 4; q++) cacc[nt][q] = 0.f;

        const int prow = (w >> 2) * 16 + l4;     // P rows for this warp
        const int nbase = (w & 3) * 16;          // d base

#pragma unroll 1
        for (int ch = 0; ch < 8; ch++) {
            const int vb = (ch & 1) ? OFF_K1 : OFF_K0;
            if (ch < 7) {
                const __half* vgc = vg + (size_t)(ch + 1) * 128 * HD;
#pragma unroll
                for (int it = 0; it < 8; it++) {
                    int s0 = it * 16 + (tid >> 5) * 2, dp = tid & 31;
                    pv0[it] = *(const uint32_t*)(vgc + (size_t)s0 * HD + dp * 2);
                    pv1[it] = *(const uint32_t*)(vgc + (size_t)(s0 + 1) * HD + dp * 2);
                }
            }

#pragma unroll
            for (int ks = 0; ks < 8; ks++) {
                const int wi = ch * 128 + ks * 16 + 2 * lc;
                float2 f0 = *(float2*)(sm + sc_byte(prow, wi));
                float2 f1 = *(float2*)(sm + sc_byte(prow + 8, wi));
                float2 f2 = *(float2*)(sm + sc_byte(prow, wi + 8));
                float2 f3 = *(float2*)(sm + sc_byte(prow + 8, wi + 8));
                uint32_t a0 = h2u(__floats2half2_rn(f0.x, f0.y));
                uint32_t a1 = h2u(__floats2half2_rn(f1.x, f1.y));
                uint32_t a2 = h2u(__floats2half2_rn(f2.x, f2.y));
                uint32_t a3 = h2u(__floats2half2_rn(f3.x, f3.y));
#pragma unroll
                for (int nt = 0; nt < 2; nt++) {
                    int d = nbase + nt * 8 + l4;
                    uint32_t b0 = *(uint32_t*)(sm + vb + d * 276 + (ks * 8 + lc) * 4);
                    uint32_t b1 = *(uint32_t*)(sm + vb + d * 276 + (ks * 8 + 4 + lc) * 4);
                    mma16(cacc[nt], a0, a1, a2, a3, b0, b1);
                }
            }

            if (ch < 7) {
                const int nb = (ch & 1) ? OFF_K0 : OFF_K1;
#pragma unroll
                for (int it = 0; it < 8; it++) {
                    int s0 = it * 16 + (tid >> 5) * 2, dp = tid & 31;
                    *(uint32_t*)(sm + nb + (2 * dp) * 276 + (s0 >> 1) * 4) =
                        __byte_perm(pv0[it], pv1[it], 0x5410);
                    *(uint32_t*)(sm + nb + (2 * dp + 1) * 276 + (s0 >> 1) * 4) =
                        __byte_perm(pv0[it], pv1[it], 0x7632);
                }
            }
            __syncthreads();
        }

        // ---- write ctx tile (fp16) for this head ----
#pragma unroll
        for (int nt = 0; nt < 2; nt++) {
            int d0 = nbase + nt * 8 + 2 * lc;
            __half2 lo = __floats2half2_rn(cacc[nt][0], cacc[nt][1]);
            __half2 hi = __floats2half2_rn(cacc[nt][2], cacc[nt][3]);
            *(__half2*)(g_ctx_h + ((size_t)(t0 + prow) * BSZb + b) * EMB + h * 64 + d0) = lo;
            *(__half2*)(g_ctx_h + ((size_t)(t0 + prow + 8) * BSZb + b) * EMB + h * 64 + d0) = hi;
        }
    }

    // ---- write avg ----
    float* arow = avg_out + ((size_t)b * TGT + t0 + srow) * SRC;
#pragma unroll
    for (int j = 0; j < 128; j++)
        arow[j * 8 + ssub] = avg[j] * (1.0f / NH);
}

// ===========================================================================
// Projection GEMM (fp16 mma.sync): C[m,n] = sum_k A[m,k]*B[n,k]
// MODE: 1=Qproj 2=Kproj 3=Vproj 5=outproj (A fp16 from g_ctx_h)
// ===========================================================================
template <int BM, int BN, int WM, int WN, int MODE>
__global__ void __launch_bounds__(256)
mma_gemm(const float* __restrict__ A, int lda,
         const float* __restrict__ B, int ldb,
         const float* __restrict__ bias,
         float* __restrict__ C, int K)
{
    constexpr bool A_HALF = (MODE == 5);
    constexpr int WTM = BM / WM, WTN = BN / WN;
    constexpr int MT = WTM / 16, NT = WTN / 8;

    __shared__ uint32_t As[2][BM][12];
    __shared__ uint32_t Bs[2][BN][12];

    const __half* Aph = nullptr;
    const float* Apf = nullptr;
    const float* Bpf = B;
    if constexpr (MODE == 5) Aph = g_ctx_h;
    else Apf = A;

    const int bm = blockIdx.y * BM;
    const int bn = blockIdx.x * BN;
    const int tid = threadIdx.x;
    const int lane = tid & 31;
    const int wid = tid >> 5;
    const int wm = wid / WN;
    const int wn = wid % WN;

    float acc[MT][NT][4];
#pragma unroll
    for (int i = 0; i < MT; i++)
#pragma unroll
        for (int j = 0; j < NT; j++)
#pragma unroll
            for (int q = 0; q < 4; q++) acc[i][j][q] = 0.0f;

    const int NC = K / 16;

    uint4 pha;  float4 pfa[2];
    float4 pfb[2];

    auto fetchA = [&](int ch) {
        if constexpr (A_HALF) {
            int r = tid >> 1, h8 = tid & 1;
            pha = *(const uint4*)(Aph + (size_t)(bm + r) * lda + ch * 16 + h8 * 8);
        } else {
#pragma unroll
            for (int it = 0; it < 2; it++) {
                int g = tid + it * 256, r = g >> 2, kq = g & 3;
                pfa[it] = *(const float4*)(Apf + (size_t)(bm + r) * lda + ch * 16 + kq * 4);
            }
        }
    };
    auto fetchB = [&](int ch) {
#pragma unroll
        for (int it = 0; it < 2; it++) {
            int g = tid + it * 256, r = g >> 2, kq = g & 3;
            pfb[it] = *(const float4*)(Bpf + (size_t)(bn + r) * ldb + ch * 16 + kq * 4);
        }
    };
    auto storeA = [&](int buf) {
        if constexpr (A_HALF) {
            int r = tid >> 1, h8 = tid & 1;
            *(uint4*)&As[buf][r][h8 * 4] = pha;
        } else {
#pragma unroll
            for (int it = 0; it < 2; it++) {
                int g = tid + it * 256, r = g >> 2, kq = g & 3;
                As[buf][r][kq * 2]     = h2u(__floats2half2_rn(pfa[it].x, pfa[it].y));
                As[buf][r][kq * 2 + 1] = h2u(__floats2half2_rn(pfa[it].z, pfa[it].w));
            }
        }
    };
    auto storeB = [&](int buf) {
#pragma unroll
        for (int it = 0; it < 2; it++) {
            int g = tid + it * 256, r = g >> 2, kq = g & 3;
            Bs[buf][r][kq * 2]     = h2u(__floats2half2_rn(pfb[it].x, pfb[it].y));
            Bs[buf][r][kq * 2 + 1] = h2u(__floats2half2_rn(pfb[it].z, pfb[it].w));
        }
    };

    fetchA(0); fetchB(0);
    storeA(0); storeB(0);
    __syncthreads();

    for (int ch = 0; ch < NC; ch++) {
        const int buf = ch & 1;
        if (ch + 1 < NC) { fetchA(ch + 1); fetchB(ch + 1); }

        const int kq = lane & 3;
        uint32_t bf[NT][2];
#pragma unroll
        for (int nt = 0; nt < NT; nt++) {
            int n = wn * WTN + nt * 8 + (lane >> 2);
            bf[nt][0] = Bs[buf][n][kq];
            bf[nt][1] = Bs[buf][n][kq + 4];
        }
#pragma unroll
        for (int mt = 0; mt < MT; mt++) {
            int m = wm * WTM + mt * 16 + (lane >> 2);
            uint32_t a0 = As[buf][m][kq];
            uint32_t a1 = As[buf][m + 8][kq];
            uint32_t a2 = As[buf][m][kq + 4];
            uint32_t a3 = As[buf][m + 8][kq + 4];
#pragma unroll
            for (int nt = 0; nt < NT; nt++)
                mma16(acc[mt][nt], a0, a1, a2, a3, bf[nt][0], bf[nt][1]);
        }

        if (ch + 1 < NC) {
            storeA(buf ^ 1);
            storeB(buf ^ 1);
            __syncthreads();
        }
    }

    // epilogue
#pragma unroll
    for (int mt = 0; mt < MT; mt++) {
#pragma unroll
        for (int nt = 0; nt < NT; nt++) {
            const int r0 = bm + wm * WTM + mt * 16 + (lane >> 2);
            const int c0 = bn + wn * WTN + nt * 8 + 2 * (lane & 3);
            const float* a4 = acc[mt][nt];
#pragma unroll
            for (int half = 0; half < 2; half++) {
                const int r = r0 + half * 8;
                const float v0 = a4[half * 2 + 0];
                const float v1 = a4[half * 2 + 1];
                if constexpr (MODE == 5) {
                    float2 wv = { v0 + bias[c0], v1 + bias[c0 + 1] };
                    *(float2*)(C + (size_t)r * EMB + c0) = wv;
                } else if constexpr (MODE == 1) {
                    int t = r >> 2, b = r & 3, hh = c0 >> 6, d = c0 & 63;
                    __half2 wv = __floats2half2_rn((v0 + bias[c0]) * 0.125f,
                                                   (v1 + bias[c0 + 1]) * 0.125f);
                    *(__half2*)(g_q + (((size_t)(b * NH + hh)) * TGT + t) * HD + d) = wv;
                } else if constexpr (MODE == 2) {
                    int s = r >> 2, b = r & 3, hh = c0 >> 6, d = c0 & 63;
                    __half2 wv = __floats2half2_rn(v0 + bias[c0], v1 + bias[c0 + 1]);
                    *(__half2*)(g_k + (((size_t)(b * NH + hh)) * SRC + s) * HD + d) = wv;
                } else { // MODE == 3
                    int s = r >> 2, b = r & 3, hh = c0 >> 6, d = c0 & 63;
                    __half2 wv = __floats2half2_rn(v0 + bias[c0], v1 + bias[c0 + 1]);
                    *(__half2*)(g_v + (((size_t)(b * NH + hh)) * SRC + s) * HD + d) = wv;
                }
            }
        }
    }
}

// ---------------------------------------------------------------------------
extern "C" void kernel_launch(void* const* d_in, const int* in_sizes, int n_in,
                              void* d_out, int out_size)
{
    const float* query = (const float*)d_in[0];
    const float* key   = (const float*)d_in[1];
    const float* hard  = (const float*)d_in[2];
    const float* W     = (const float*)d_in[3];
    const float* bias  = (const float*)d_in[4];
    const float* Wo    = (const float*)d_in[5];
    const float* bo    = (const float*)d_in[6];
    float* out = (float*)d_out;
    float* avg_out = out + (size_t)TGT * BSZb * EMB;

    const int MTB = TGT * BSZb;  // 4096

    cudaFuncSetAttribute(fused_attn_kernel,
                         cudaFuncAttributeMaxDynamicSharedMemorySize, SMEM_FUSED);

    // 1..3: QKV projections
    {
        dim3 grid(EMB / 128, MTB / 128);
        mma_gemm<128, 128, 2, 4, 1><<<grid, 256>>>(query, EMB, W, EMB, bias, nullptr, EMB);
        mma_gemm<128, 128, 2, 4, 2><<<grid, 256>>>(key, EMB, W + (size_t)EMB * EMB, EMB, bias + EMB, nullptr, EMB);
        mma_gemm<128, 128, 2, 4, 3><<<grid, 256>>>(key, EMB, W + (size_t)2 * EMB * EMB, EMB, bias + 2 * EMB, nullptr, EMB);
    }
    // 4: fused attention (scores + softmax + mask + avg + PV)
    {
        dim3 grid(TGT / 32, BSZb);
        fused_attn_kernel<<<grid, 256, SMEM_FUSED>>>(hard, avg_out);
    }
    // 5: out projection
    {
        dim3 grid(EMB / 128, MTB / 128);
        mma_gemm<128, 128, 2, 4, 5><<<grid, 256>>>(nullptr, EMB, Wo, EMB, bo, out, EMB);
    }
}

// round 8
// speedup vs baseline: 1.0344x; 1.0344x over previous
#include <cuda_runtime.h>
#include <cuda_fp16.h>
#include <cstdint>

#define TGT 1024
#define SRC 1024
#define BSZb 4
#define EMB 1024
#define NH 16
#define HD 64

// -------- device scratch --------
__device__ __half g_q[BSZb * NH * TGT * HD];        // (b,h,t,d) scaled, fp16
__device__ __half g_k[BSZb * NH * SRC * HD];        // (b,h,s,d) fp16
__device__ __half g_v[BSZb * NH * SRC * HD];        // (b,h,s,d) fp16
__device__ __half g_ctx_h[TGT * BSZb * EMB];        // (t,b,e) fp16

__device__ __forceinline__ uint32_t h2u(__half2 h) {
    return *reinterpret_cast<uint32_t*>(&h);
}
__device__ __forceinline__ uint32_t smem_u32(const void* p) {
    uint32_t a;
    asm("{ .reg .u64 t; cvta.to.shared.u64 t, %1; cvt.u32.u64 %0, t; }" : "=r"(a) : "l"(p));
    return a;
}
__device__ __forceinline__ void mma16(float* d, uint32_t a0, uint32_t a1,
                                      uint32_t a2, uint32_t a3,
                                      uint32_t b0, uint32_t b1) {
    asm volatile(
        "mma.sync.aligned.m16n8k16.row.col.f32.f16.f16.f32 "
        "{%0,%1,%2,%3}, {%4,%5,%6,%7}, {%8,%9}, {%0,%1,%2,%3};"
        : "+f"(d[0]), "+f"(d[1]), "+f"(d[2]), "+f"(d[3])
        : "r"(a0), "r"(a1), "r"(a2), "r"(a3), "r"(b0), "r"(b1));
}
__device__ __forceinline__ void ldsm4(uint32_t* r, uint32_t addr) {
    asm volatile("ldmatrix.sync.aligned.m8n8.x4.shared.b16 {%0,%1,%2,%3}, [%4];"
        : "=r"(r[0]), "=r"(r[1]), "=r"(r[2]), "=r"(r[3]) : "r"(addr));
}
__device__ __forceinline__ void ldsm4t(uint32_t* r, uint32_t addr) {
    asm volatile("ldmatrix.sync.aligned.m8n8.x4.trans.shared.b16 {%0,%1,%2,%3}, [%4];"
        : "=r"(r[0]), "=r"(r[1]), "=r"(r[2]), "=r"(r[3]) : "r"(addr));
}
__device__ __forceinline__ void cp16(uint32_t dst, const void* src) {
    asm volatile("cp.async.cg.shared.global [%0], [%1], 16;" :: "r"(dst), "l"(src));
}
__device__ __forceinline__ void cp_commit() {
    asm volatile("cp.async.commit_group;" ::: "memory");
}
template <int N>
__device__ __forceinline__ void cp_wait() {
    asm volatile("cp.async.wait_group %0;" :: "n"(N) : "memory");
}

// ===========================================================================
// Fused middle: per CTA = (b, 16 t-rows), loop 16 heads:
//   scores (QK^T) -> sc SMEM fp32 -> softmax+mask (avg in regs)
//   -> PV from sc -> ctx fp16.  No scores/P in gmem.
// ===========================================================================
#define OFF_SC 0                      // 16 x 1024 fp32 swizzled     65536
#define OFF_Q  65536                  // 16 x 64 fp16 swizzled        2048
#define OFF_K0 67584                  // 128 x 64 fp16 swizzled      16384
#define OFF_K1 83968
#define SMEM_FUSED 100352

__device__ __forceinline__ int sc_byte(int r, int w) {
    return OFF_SC + (r << 12) + ((((w >> 2) ^ (r & 7)) << 4) | ((w & 3) << 2));
}

__global__ void __launch_bounds__(256, 2)
fused_attn_kernel(const float* __restrict__ hard, float* __restrict__ avg_out)
{
    extern __shared__ char sm[];
    const uint32_t sb = smem_u32(sm);
    const int b = blockIdx.y;
    const int t0 = blockIdx.x * 16;
    const int tid = threadIdx.x;
    const int lane = tid & 31;
    const int w = tid >> 5;          // 0..7
    const int l4 = lane >> 2;        // 0..7
    const int lc = lane & 3;         // 0..3

    // softmax ownership: row (0..15), 64 cols strided 16
    const int srow = tid >> 4;
    const int ssub = tid & 15;

    float avg[64];
#pragma unroll
    for (int j = 0; j < 64; j++) avg[j] = 0.f;
    uint32_t mbits[2] = {0u, 0u};

    // ldmatrix lane addressing pieces
    const int lr8 = ((lane >> 3) & 1) * 8 + (lane & 7);  // row within 16
    const int ghi = lane >> 4;                           // k-half select

#pragma unroll 1
    for (int h = 0; h < NH; h++) {
        const size_t bh = (size_t)(b * NH + h);
        const __half* qg = g_q + bh * (TGT * HD) + (size_t)t0 * HD;
        const __half* kg = g_k + bh * (SRC * HD);
        const __half* vg = g_v + bh * (SRC * HD);

        __syncthreads();   // prior head fully done with sc / kv buffers

        // ---- cp.async: Q tile + K chunk 0 ----
        if (tid < 128) {
            int r = tid >> 3, g = tid & 7;
            cp16(sb + OFF_Q + r * 128 + ((g ^ (r & 7)) << 4), qg + r * HD + g * 8);
        }
#pragma unroll
        for (int i = 0; i < 4; i++) {
            int idx = tid + i * 256, r = idx >> 3, g = idx & 7;
            cp16(sb + OFF_K0 + r * 128 + ((g ^ (r & 7)) << 4), kg + (size_t)r * HD + g * 8);
        }
        cp_commit();
        cp_wait<0>();
        __syncthreads();

        // ---- Q fragments (held in regs for whole phase A) ----
        uint32_t qf[4][4];
#pragma unroll
        for (int ks = 0; ks < 4; ks++) {
            int gr = ks * 2 + ghi;
            ldsm4(qf[ks], sb + OFF_Q + lr8 * 128 + ((gr ^ (lr8 & 7)) << 4));
        }

        // ---- phase A: scores, 8 s-chunks of 128 ----
#pragma unroll 1
        for (int ch = 0; ch < 8; ch++) {
            const uint32_t kb = sb + ((ch & 1) ? OFF_K1 : OFF_K0);
            if (ch < 7) {
                const __half* kgc = kg + (size_t)(ch + 1) * 128 * HD;
                const uint32_t nb = sb + ((ch & 1) ? OFF_K0 : OFF_K1);
#pragma unroll
                for (int i = 0; i < 4; i++) {
                    int idx = tid + i * 256, r = idx >> 3, g = idx & 7;
                    cp16(nb + r * 128 + ((g ^ (r & 7)) << 4), kgc + (size_t)r * HD + g * 8);
                }
                cp_commit();
            }

            float acc[2][4];
#pragma unroll
            for (int nt = 0; nt < 2; nt++)
#pragma unroll
                for (int q = 0; q < 4; q++) acc[nt][q] = 0.f;

#pragma unroll
            for (int ks = 0; ks < 4; ks++) {
                uint32_t kf[4];
                int s = w * 16 + lr8;
                int gr = ks * 2 + ghi;
                ldsm4(kf, kb + s * 128 + ((gr ^ (s & 7)) << 4));
                mma16(acc[0], qf[ks][0], qf[ks][1], qf[ks][2], qf[ks][3], kf[0], kf[2]);
                mma16(acc[1], qf[ks][0], qf[ks][1], qf[ks][2], qf[ks][3], kf[1], kf[3]);
            }

            // store scores tile (rows l4 / l4+8, cols of this warp's n16)
#pragma unroll
            for (int nt = 0; nt < 2; nt++) {
                int wi = ch * 128 + w * 16 + nt * 8 + 2 * lc;
                *(float2*)(sm + sc_byte(l4, wi)) = make_float2(acc[nt][0], acc[nt][1]);
                *(float2*)(sm + sc_byte(l4 + 8, wi)) = make_float2(acc[nt][2], acc[nt][3]);
            }

            cp_wait<0>();   // prefetch for next chunk must have landed
            __syncthreads();
        }

        // ---- softmax + mask + avg ----
        {
            float m = -1e30f;
#pragma unroll
            for (int j = 0; j < 64; j++)
                m = fmaxf(m, *(float*)(sm + sc_byte(srow, j * 16 + ssub)));
#pragma unroll
            for (int o = 1; o < 16; o <<= 1)
                m = fmaxf(m, __shfl_xor_sync(0xffffffffu, m, o));

            float s = 0.f;
#pragma unroll
            for (int j = 0; j < 64; j++) {
                float* p = (float*)(sm + sc_byte(srow, j * 16 + ssub));
                float e = __expf(*p - m);
                *p = e;
                s += e;
            }
#pragma unroll
            for (int o = 1; o < 16; o <<= 1)
                s += __shfl_xor_sync(0xffffffffu, s, o);
            const float inv = 1.0f / s;

            if (h == 0) {
                const float* mrow = hard + ((size_t)b * TGT + t0 + srow) * SRC;
#pragma unroll
                for (int j = 0; j < 64; j++) {
                    uint32_t bit = (mrow[j * 16 + ssub] > 0.5f) ? 1u : 0u;
                    mbits[j >> 5] |= bit << (j & 31);
                    float* p = (float*)(sm + sc_byte(srow, j * 16 + ssub));
                    float pv = (*p) * inv * (float)bit;
                    *p = pv;
                    avg[j] += pv;
                }
            } else {
#pragma unroll
                for (int j = 0; j < 64; j++) {
                    float mk = (float)((mbits[j >> 5] >> (j & 31)) & 1u);
                    float* p = (float*)(sm + sc_byte(srow, j * 16 + ssub));
                    float pv = (*p) * inv * mk;
                    *p = pv;
                    avg[j] += pv;
                }
            }
        }
        __syncthreads();

        // ---- phase C: ctx = P V, 8 s-chunks; V frags via ldmatrix.trans ----
        {   // V chunk 0
#pragma unroll
            for (int i = 0; i < 4; i++) {
                int idx = tid + i * 256, r = idx >> 3, g = idx & 7;
                cp16(sb + OFF_K0 + r * 128 + ((g ^ (r & 7)) << 4), vg + (size_t)r * HD + g * 8);
            }
            cp_commit();
            cp_wait<0>();
            __syncthreads();
        }

        float cacc[4] = {0.f, 0.f, 0.f, 0.f};

#pragma unroll 1
        for (int ch = 0; ch < 8; ch++) {
            const uint32_t vb = sb + ((ch & 1) ? OFF_K1 : OFF_K0);
            if (ch < 7) {
                const __half* vgc = vg + (size_t)(ch + 1) * 128 * HD;
                const uint32_t nb = sb + ((ch & 1) ? OFF_K0 : OFF_K1);
#pragma unroll
                for (int i = 0; i < 4; i++) {
                    int idx = tid + i * 256, r = idx >> 3, g = idx & 7;
                    cp16(nb + r * 128 + ((g ^ (r & 7)) << 4), vgc + (size_t)r * HD + g * 8);
                }
                cp_commit();
            }

#pragma unroll
            for (int ks2 = 0; ks2 < 4; ks2++) {
                uint32_t vf[4];
                int s = ks2 * 32 + lane;     // 32 consecutive s rows
                ldsm4t(vf, vb + s * 128 + ((w ^ (s & 7)) << 4));
#pragma unroll
                for (int t = 0; t < 2; t++) {
                    int wi = ch * 128 + (ks2 * 2 + t) * 16 + 2 * lc;
                    float2 f0 = *(float2*)(sm + sc_byte(l4, wi));
                    float2 f1 = *(float2*)(sm + sc_byte(l4 + 8, wi));
                    float2 f2 = *(float2*)(sm + sc_byte(l4, wi + 8));
                    float2 f3 = *(float2*)(sm + sc_byte(l4 + 8, wi + 8));
                    mma16(cacc,
                          h2u(__floats2half2_rn(f0.x, f0.y)),
                          h2u(__floats2half2_rn(f1.x, f1.y)),
                          h2u(__floats2half2_rn(f2.x, f2.y)),
                          h2u(__floats2half2_rn(f3.x, f3.y)),
                          vf[t * 2], vf[t * 2 + 1]);
                }
            }

            cp_wait<0>();   // prefetch for next chunk must have landed
            __syncthreads();
        }

        // ---- write ctx (fp16): warp w owns d = w*8 .. w*8+7 ----
        {
            int e = h * 64 + w * 8 + 2 * lc;
            *(__half2*)(g_ctx_h + ((size_t)(t0 + l4) * BSZb + b) * EMB + e) =
                __floats2half2_rn(cacc[0], cacc[1]);
            *(__half2*)(g_ctx_h + ((size_t)(t0 + l4 + 8) * BSZb + b) * EMB + e) =
                __floats2half2_rn(cacc[2], cacc[3]);
        }
    }

    // ---- write avg ----
    float* arow = avg_out + ((size_t)b * TGT + t0 + srow) * SRC;
#pragma unroll
    for (int j = 0; j < 64; j++)
        arow[j * 16 + ssub] = avg[j] * (1.0f / NH);
}

// ===========================================================================
// Projection GEMM (fp16 mma.sync): C[m,n] = sum_k A[m,k]*B[n,k]
// MODE: 1=Qproj 2=Kproj 3=Vproj 5=outproj (A fp16 from g_ctx_h)
// ===========================================================================
template <int BM, int BN, int WM, int WN, int MODE>
__global__ void __launch_bounds__(256)
mma_gemm(const float* __restrict__ A, int lda,
         const float* __restrict__ B, int ldb,
         const float* __restrict__ bias,
         float* __restrict__ C, int K)
{
    constexpr bool A_HALF = (MODE == 5);
    constexpr int WTM = BM / WM, WTN = BN / WN;
    constexpr int MT = WTM / 16, NT = WTN / 8;

    __shared__ uint32_t As[2][BM][12];
    __shared__ uint32_t Bs[2][BN][12];

    const __half* Aph = nullptr;
    const float* Apf = nullptr;
    const float* Bpf = B;
    if constexpr (MODE == 5) Aph = g_ctx_h;
    else Apf = A;

    const int bm = blockIdx.y * BM;
    const int bn = blockIdx.x * BN;
    const int tid = threadIdx.x;
    const int lane = tid & 31;
    const int wid = tid >> 5;
    const int wm = wid / WN;
    const int wn = wid % WN;

    float acc[MT][NT][4];
#pragma unroll
    for (int i = 0; i < MT; i++)
#pragma unroll
        for (int j = 0; j < NT; j++)
#pragma unroll
            for (int q = 0; q < 4; q++) acc[i][j][q] = 0.0f;

    const int NC = K / 16;

    uint4 pha;  float4 pfa[2];
    float4 pfb[2];

    auto fetchA = [&](int ch) {
        if constexpr (A_HALF) {
            int r = tid >> 1, h8 = tid & 1;
            pha = *(const uint4*)(Aph + (size_t)(bm + r) * lda + ch * 16 + h8 * 8);
        } else {
#pragma unroll
            for (int it = 0; it < 2; it++) {
                int g = tid + it * 256, r = g >> 2, kq = g & 3;
                pfa[it] = *(const float4*)(Apf + (size_t)(bm + r) * lda + ch * 16 + kq * 4);
            }
        }
    };
    auto fetchB = [&](int ch) {
#pragma unroll
        for (int it = 0; it < 2; it++) {
            int g = tid + it * 256, r = g >> 2, kq = g & 3;
            pfb[it] = *(const float4*)(Bpf + (size_t)(bn + r) * ldb + ch * 16 + kq * 4);
        }
    };
    auto storeA = [&](int buf) {
        if constexpr (A_HALF) {
            int r = tid >> 1, h8 = tid & 1;
            *(uint4*)&As[buf][r][h8 * 4] = pha;
        } else {
#pragma unroll
            for (int it = 0; it < 2; it++) {
                int g = tid + it * 256, r = g >> 2, kq = g & 3;
                As[buf][r][kq * 2]     = h2u(__floats2half2_rn(pfa[it].x, pfa[it].y));
                As[buf][r][kq * 2 + 1] = h2u(__floats2half2_rn(pfa[it].z, pfa[it].w));
            }
        }
    };
    auto storeB = [&](int buf) {
#pragma unroll
        for (int it = 0; it < 2; it++) {
            int g = tid + it * 256, r = g >> 2, kq = g & 3;
            Bs[buf][r][kq * 2]     = h2u(__floats2half2_rn(pfb[it].x, pfb[it].y));
            Bs[buf][r][kq * 2 + 1] = h2u(__floats2half2_rn(pfb[it].z, pfb[it].w));
        }
    };

    fetchA(0); fetchB(0);
    storeA(0); storeB(0);
    __syncthreads();

    for (int ch = 0; ch < NC; ch++) {
        const int buf = ch & 1;
        if (ch + 1 < NC) { fetchA(ch + 1); fetchB(ch + 1); }

        const int kq = lane & 3;
        uint32_t bf[NT][2];
#pragma unroll
        for (int nt = 0; nt < NT; nt++) {
            int n = wn * WTN + nt * 8 + (lane >> 2);
            bf[nt][0] = Bs[buf][n][kq];
            bf[nt][1] = Bs[buf][n][kq + 4];
        }
#pragma unroll
        for (int mt = 0; mt < MT; mt++) {
            int m = wm * WTM + mt * 16 + (lane >> 2);
            uint32_t a0 = As[buf][m][kq];
            uint32_t a1 = As[buf][m + 8][kq];
            uint32_t a2 = As[buf][m][kq + 4];
            uint32_t a3 = As[buf][m + 8][kq + 4];
#pragma unroll
            for (int nt = 0; nt < NT; nt++)
                mma16(acc[mt][nt], a0, a1, a2, a3, bf[nt][0], bf[nt][1]);
        }

        if (ch + 1 < NC) {
            storeA(buf ^ 1);
            storeB(buf ^ 1);
            __syncthreads();
        }
    }

    // epilogue
#pragma unroll
    for (int mt = 0; mt < MT; mt++) {
#pragma unroll
        for (int nt = 0; nt < NT; nt++) {
            const int r0 = bm + wm * WTM + mt * 16 + (lane >> 2);
            const int c0 = bn + wn * WTN + nt * 8 + 2 * (lane & 3);
            const float* a4 = acc[mt][nt];
#pragma unroll
            for (int half = 0; half < 2; half++) {
                const int r = r0 + half * 8;
                const float v0 = a4[half * 2 + 0];
                const float v1 = a4[half * 2 + 1];
                if constexpr (MODE == 5) {
                    float2 wv = { v0 + bias[c0], v1 + bias[c0 + 1] };
                    *(float2*)(C + (size_t)r * EMB + c0) = wv;
                } else if constexpr (MODE == 1) {
                    int t = r >> 2, b = r & 3, hh = c0 >> 6, d = c0 & 63;
                    __half2 wv = __floats2half2_rn((v0 + bias[c0]) * 0.125f,
                                                   (v1 + bias[c0 + 1]) * 0.125f);
                    *(__half2*)(g_q + (((size_t)(b * NH + hh)) * TGT + t) * HD + d) = wv;
                } else if constexpr (MODE == 2) {
                    int s = r >> 2, b = r & 3, hh = c0 >> 6, d = c0 & 63;
                    __half2 wv = __floats2half2_rn(v0 + bias[c0], v1 + bias[c0 + 1]);
                    *(__half2*)(g_k + (((size_t)(b * NH + hh)) * SRC + s) * HD + d) = wv;
                } else { // MODE == 3
                    int s = r >> 2, b = r & 3, hh = c0 >> 6, d = c0 & 63;
                    __half2 wv = __floats2half2_rn(v0 + bias[c0], v1 + bias[c0 + 1]);
                    *(__half2*)(g_v + (((size_t)(b * NH + hh)) * SRC + s) * HD + d) = wv;
                }
            }
        }
    }
}

// ---------------------------------------------------------------------------
extern "C" void kernel_launch(void* const* d_in, const int* in_sizes, int n_in,
                              void* d_out, int out_size)
{
    const float* query = (const float*)d_in[0];
    const float* key   = (const float*)d_in[1];
    const float* hard  = (const float*)d_in[2];
    const float* W     = (const float*)d_in[3];
    const float* bias  = (const float*)d_in[4];
    const float* Wo    = (const float*)d_in[5];
    const float* bo    = (const float*)d_in[6];
    float* out = (float*)d_out;
    float* avg_out = out + (size_t)TGT * BSZb * EMB;

    const int MTB = TGT * BSZb;  // 4096

    cudaFuncSetAttribute(fused_attn_kernel,
                         cudaFuncAttributeMaxDynamicSharedMemorySize, SMEM_FUSED);

    // 1..3: QKV projections
    {
        dim3 grid(EMB / 128, MTB / 128);
        mma_gemm<128, 128, 2, 4, 1><<<grid, 256>>>(query, EMB, W, EMB, bias, nullptr, EMB);
        mma_gemm<128, 128, 2, 4, 2><<<grid, 256>>>(key, EMB, W + (size_t)EMB * EMB, EMB, bias + EMB, nullptr, EMB);
        mma_gemm<128, 128, 2, 4, 3><<<grid, 256>>>(key, EMB, W + (size_t)2 * EMB * EMB, EMB, bias + 2 * EMB, nullptr, EMB);
    }
    // 4: fused attention middle
    {
        dim3 grid(TGT / 16, BSZb);
        fused_attn_kernel<<<grid, 256, SMEM_FUSED>>>(hard, avg_out);
    }
    // 5: out projection
    {
        dim3 grid(EMB / 128, MTB / 128);
        mma_gemm<128, 128, 2, 4, 5><<<grid, 256>>>(nullptr, EMB, Wo, EMB, bo, out, EMB);
    }
}

// round 12
// speedup vs baseline: 1.2851x; 1.2423x over previous
#include <cuda_runtime.h>
#include <cuda_fp16.h>
#include <cstdint>

#define TGT 1024
#define SRC 1024
#define BSZb 4
#define EMB 1024
#define NH 16
#define HD 64

// -------- device scratch --------
__device__ __half g_qin[TGT * BSZb * EMB];          // query fp16
__device__ __half g_kin[SRC * BSZb * EMB];          // key fp16
__device__ __half g_w16[3 * EMB * EMB];             // in_proj_weight fp16
__device__ __half g_wo16[EMB * EMB];                // out_proj_weight fp16
__device__ __half g_q[BSZb * NH * TGT * HD];        // (b,h,t,d) scaled fp16
__device__ __half g_k[BSZb * NH * SRC * HD];        // (b,h,s,d) fp16
__device__ __half g_v[BSZb * NH * SRC * HD];        // (b,h,s,d) fp16
__device__ float  g_scores[(size_t)BSZb * NH * TGT * SRC]; // fp32 scores
__device__ __half g_p[(size_t)BSZb * NH * TGT * SRC];      // masked P fp16
__device__ __half g_ctx_h[TGT * BSZb * EMB];        // (t,b,e) fp16

__device__ __forceinline__ uint32_t h2u(__half2 h) {
    return *reinterpret_cast<uint32_t*>(&h);
}
__device__ __forceinline__ uint32_t smem_u32(const void* p) {
    uint32_t a;
    asm("{ .reg .u64 t; cvta.to.shared.u64 t, %1; cvt.u32.u64 %0, t; }" : "=r"(a) : "l"(p));
    return a;
}
__device__ __forceinline__ void mma16(float* d, uint32_t a0, uint32_t a1,
                                      uint32_t a2, uint32_t a3,
                                      uint32_t b0, uint32_t b1) {
    asm volatile(
        "mma.sync.aligned.m16n8k16.row.col.f32.f16.f16.f32 "
        "{%0,%1,%2,%3}, {%4,%5,%6,%7}, {%8,%9}, {%0,%1,%2,%3};"
        : "+f"(d[0]), "+f"(d[1]), "+f"(d[2]), "+f"(d[3])
        : "r"(a0), "r"(a1), "r"(a2), "r"(a3), "r"(b0), "r"(b1));
}
__device__ __forceinline__ void ldsm4(uint32_t* r, uint32_t addr) {
    asm volatile("ldmatrix.sync.aligned.m8n8.x4.shared.b16 {%0,%1,%2,%3}, [%4];"
        : "=r"(r[0]), "=r"(r[1]), "=r"(r[2]), "=r"(r[3]) : "r"(addr));
}
__device__ __forceinline__ void ldsm4t(uint32_t* r, uint32_t addr) {
    asm volatile("ldmatrix.sync.aligned.m8n8.x4.trans.shared.b16 {%0,%1,%2,%3}, [%4];"
        : "=r"(r[0]), "=r"(r[1]), "=r"(r[2]), "=r"(r[3]) : "r"(addr));
}
__device__ __forceinline__ void cp16(uint32_t dst, const void* src) {
    asm volatile("cp.async.cg.shared.global [%0], [%1], 16;" :: "r"(dst), "l"(src));
}
__device__ __forceinline__ void cp_commit() {
    asm volatile("cp.async.commit_group;" ::: "memory");
}
template <int N>
__device__ __forceinline__ void cp_wait() {
    asm volatile("cp.async.wait_group %0;" :: "n"(N) : "memory");
}

// ---------------------------------------------------------------------------
// fp32 -> fp16 conversion (vectorized)
// ---------------------------------------------------------------------------
__global__ void __launch_bounds__(256)
cvt_kernel(const float4* __restrict__ in, uint2* __restrict__ out, int n4)
{
    int i = blockIdx.x * 256 + threadIdx.x;
    if (i < n4) {
        float4 v = in[i];
        __half2 lo = __floats2half2_rn(v.x, v.y);
        __half2 hi = __floats2half2_rn(v.z, v.w);
        out[i] = make_uint2(h2u(lo), h2u(hi));
    }
}

// ===========================================================================
// fp16 GEMM, cp.async + ldmatrix, BK=64, 128B swizzled SMEM rows.
// C[m,n] = sum_k A[m,k]*B[n,k].
// MODE: 0=scores 1=Qproj 2=Kproj 3=Vproj 4=PV(B=V, ldsm.trans) 5=outproj
// ===========================================================================
template <int BM, int BN, int WM, int WN, int MODE>
__global__ void __launch_bounds__(256)
hgemm(const float* __restrict__ bias, float* __restrict__ C,
      int K, int lda, int ldb)
{
    constexpr bool BT = (MODE == 4);
    constexpr int WTM = BM / WM, WTN = BN / WN;
    constexpr int MT = WTM / 16, NT = WTN / 8;
    constexpr int ABYTES = BM * 128;
    constexpr int BROWS = BT ? 64 : BN;
    constexpr int BBYTES = BROWS * 128;

    extern __shared__ char sm[];
    const uint32_t sA = smem_u32(sm);
    const uint32_t sB = sA + 2 * ABYTES;

    const int z = blockIdx.z;
    const __half* Ah;
    const __half* Bh;
    if constexpr (MODE == 0) { Ah = g_q + (size_t)z * TGT * HD; Bh = g_k + (size_t)z * SRC * HD; }
    else if constexpr (MODE == 4) { Ah = g_p + (size_t)z * TGT * SRC; Bh = g_v + (size_t)z * SRC * HD; }
    else if constexpr (MODE == 5) { Ah = g_ctx_h; Bh = g_wo16; }
    else if constexpr (MODE == 1) { Ah = g_qin; Bh = g_w16; }
    else if constexpr (MODE == 2) { Ah = g_kin; Bh = g_w16 + (size_t)EMB * EMB; }
    else                          { Ah = g_kin; Bh = g_w16 + (size_t)2 * EMB * EMB; }

    const int bm = blockIdx.y * BM;
    const int bn = blockIdx.x * BN;
    const int tid = threadIdx.x;
    const int lane = tid & 31;
    const int wid = tid >> 5;
    const int wm = wid / WN;
    const int wn = wid % WN;
    const int l4 = lane >> 2;
    const int lc = lane & 3;
    const int lr8 = ((lane >> 3) & 1) * 8 + (lane & 7);
    const int ghi = lane >> 4;

    float acc[MT][NT][4];
#pragma unroll
    for (int i = 0; i < MT; i++)
#pragma unroll
        for (int j = 0; j < NT; j++)
#pragma unroll
            for (int q = 0; q < 4; q++) acc[i][j][q] = 0.0f;

    const int NC = K / 64;

    auto loadA = [&](int buf, int ch) {
#pragma unroll
        for (int i = 0; i < BM * 8 / 256; i++) {
            int idx = tid + i * 256, r = idx >> 3, g = idx & 7;
            cp16(sA + buf * ABYTES + r * 128 + ((g ^ (r & 7)) << 4),
                 Ah + (size_t)(bm + r) * lda + ch * 64 + g * 8);
        }
    };
    auto loadB = [&](int buf, int ch) {
        if constexpr (BT) {
#pragma unroll
            for (int i = 0; i < 2; i++) {
                int idx = tid + i * 256, r = idx >> 3, g = idx & 7;
                cp16(sB + buf * BBYTES + r * 128 + ((g ^ (r & 7)) << 4),
                     Bh + (size_t)(ch * 64 + r) * ldb + g * 8);
            }
        } else {
#pragma unroll
            for (int i = 0; i < BROWS * 8 / 256; i++) {
                int idx = tid + i * 256, r = idx >> 3, g = idx & 7;
                cp16(sB + buf * BBYTES + r * 128 + ((g ^ (r & 7)) << 4),
                     Bh + (size_t)(bn + r) * ldb + ch * 64 + g * 8);
            }
        }
    };

    loadA(0, 0); loadB(0, 0);
    cp_commit();
    cp_wait<0>();
    __syncthreads();

    for (int ch = 0; ch < NC; ch++) {
        const int buf = ch & 1;
        if (ch + 1 < NC) {
            loadA(buf ^ 1, ch + 1);
            loadB(buf ^ 1, ch + 1);
            cp_commit();
        }
        const uint32_t bA = sA + buf * ABYTES;
        const uint32_t bB = sB + buf * BBYTES;

        if constexpr (BT) {
            // V tile (64 s-rows x 64 d). B-frags via ldmatrix.trans:
            // frag group [ks32][jj]: s rows ks32*32+lane, d granule wn*2+jj.
            uint32_t vfr[2][2][4];
#pragma unroll
            for (int ks32 = 0; ks32 < 2; ks32++)
#pragma unroll
                for (int jj = 0; jj < 2; jj++) {
                    int s = ks32 * 32 + lane;
                    int gidx = wn * 2 + jj;
                    ldsm4t(vfr[ks32][jj], bB + s * 128 + ((gidx ^ (s & 7)) << 4));
                }
#pragma unroll
            for (int ks = 0; ks < 4; ks++) {
                int kg = ks * 2 + ghi;
                int ks32 = ks >> 1, t = ks & 1;
#pragma unroll
                for (int mt = 0; mt < MT; mt++) {
                    int m = wm * WTM + mt * 16 + lr8;
                    uint32_t af[4];
                    ldsm4(af, bA + m * 128 + ((kg ^ (m & 7)) << 4));
#pragma unroll
                    for (int jj = 0; jj < 2; jj++)
                        mma16(acc[mt][jj], af[0], af[1], af[2], af[3],
                              vfr[ks32][jj][t * 2], vfr[ks32][jj][t * 2 + 1]);
                }
            }
        } else {
#pragma unroll
            for (int ks = 0; ks < 4; ks++) {
                int kg = ks * 2 + ghi;
                uint32_t bf[NT / 2][4];
#pragma unroll
                for (int np = 0; np < NT / 2; np++) {
                    int n = wn * WTN + np * 16 + lr8;
                    ldsm4(bf[np], bB + n * 128 + ((kg ^ (n & 7)) << 4));
                }
#pragma unroll
                for (int mt = 0; mt < MT; mt++) {
                    int m = wm * WTM + mt * 16 + lr8;
                    uint32_t af[4];
                    ldsm4(af, bA + m * 128 + ((kg ^ (m & 7)) << 4));
#pragma unroll
                    for (int np = 0; np < NT / 2; np++) {
                        mma16(acc[mt][2 * np],     af[0], af[1], af[2], af[3], bf[np][0], bf[np][2]);
                        mma16(acc[mt][2 * np + 1], af[0], af[1], af[2], af[3], bf[np][1], bf[np][3]);
                    }
                }
            }
        }

        if (ch + 1 < NC) {
            cp_wait<0>();
            __syncthreads();
        }
    }

    // ---- epilogue (R4-proven frag->C mapping) ----
#pragma unroll
    for (int mt = 0; mt < MT; mt++) {
#pragma unroll
        for (int nt = 0; nt < NT; nt++) {
            const int r0 = bm + wm * WTM + mt * 16 + l4;
            const int c0 = bn + wn * WTN + nt * 8 + 2 * lc;
            const float* a4 = acc[mt][nt];
#pragma unroll
            for (int half = 0; half < 2; half++) {
                const int r = r0 + half * 8;
                const float v0 = a4[half * 2 + 0];
                const float v1 = a4[half * 2 + 1];
                if constexpr (MODE == 0) {
                    *(float2*)(g_scores + (size_t)z * TGT * SRC + (size_t)r * SRC + c0) =
                        make_float2(v0, v1);
                } else if constexpr (MODE == 4) {
                    int b = z >> 4, h = z & 15;
                    *(__half2*)(g_ctx_h + ((size_t)r * BSZb + b) * EMB + h * 64 + c0) =
                        __floats2half2_rn(v0, v1);
                } else if constexpr (MODE == 5) {
                    *(float2*)(C + (size_t)r * EMB + c0) =
                        make_float2(v0 + bias[c0], v1 + bias[c0 + 1]);
                } else if constexpr (MODE == 1) {
                    int t = r >> 2, b = r & 3, hh = c0 >> 6, d = c0 & 63;
                    *(__half2*)(g_q + (((size_t)(b * NH + hh)) * TGT + t) * HD + d) =
                        __floats2half2_rn((v0 + bias[c0]) * 0.125f,
                                          (v1 + bias[c0 + 1]) * 0.125f);
                } else if constexpr (MODE == 2) {
                    int s = r >> 2, b = r & 3, hh = c0 >> 6, d = c0 & 63;
                    *(__half2*)(g_k + (((size_t)(b * NH + hh)) * SRC + s) * HD + d) =
                        __floats2half2_rn(v0 + bias[c0], v1 + bias[c0 + 1]);
                } else { // MODE == 3
                    int s = r >> 2, b = r & 3, hh = c0 >> 6, d = c0 & 63;
                    *(__half2*)(g_v + (((size_t)(b * NH + hh)) * SRC + s) * HD + d) =
                        __floats2half2_rn(v0 + bias[c0], v1 + bias[c0 + 1]);
                }
            }
        }
    }
}

// ---------------------------------------------------------------------------
// softmax -> hard mask -> P (fp16) to g_p, head-average (fp32) to avg_out
// (verbatim from R4 passing kernel)
// ---------------------------------------------------------------------------
__global__ void __launch_bounds__(256)
softmax_mask_avg_kernel(const float* __restrict__ hard, float* __restrict__ avg_out)
{
    const int t = blockIdx.x;
    const int b = blockIdx.y;
    const int tid = threadIdx.x;
    const int c = tid * 4;
    __shared__ float red[8];

    const float* mrow = hard + ((size_t)b * TGT + t) * SRC;
    float4 mask = *(const float4*)(mrow + c);
    float4 avg = { 0.f, 0.f, 0.f, 0.f };

    for (int h = 0; h < NH; h++) {
        const size_t roff = ((size_t)(b * NH + h) * TGT + t) * SRC;
        float4 v = *(const float4*)(g_scores + roff + c);

        float m = fmaxf(fmaxf(v.x, v.y), fmaxf(v.z, v.w));
#pragma unroll
        for (int o = 16; o; o >>= 1) m = fmaxf(m, __shfl_xor_sync(0xffffffffu, m, o));
        if ((tid & 31) == 0) red[tid >> 5] = m;
        __syncthreads();
        m = fmaxf(fmaxf(fmaxf(red[0], red[1]), fmaxf(red[2], red[3])),
                  fmaxf(fmaxf(red[4], red[5]), fmaxf(red[6], red[7])));
        __syncthreads();

        float e0 = __expf(v.x - m), e1 = __expf(v.y - m);
        float e2 = __expf(v.z - m), e3 = __expf(v.w - m);
        float s = e0 + e1 + e2 + e3;
#pragma unroll
        for (int o = 16; o; o >>= 1) s += __shfl_xor_sync(0xffffffffu, s, o);
        if ((tid & 31) == 0) red[tid >> 5] = s;
        __syncthreads();
        s = red[0] + red[1] + red[2] + red[3] + red[4] + red[5] + red[6] + red[7];
        __syncthreads();

        const float inv = 1.0f / s;
        float p0 = e0 * inv * mask.x, p1 = e1 * inv * mask.y;
        float p2 = e2 * inv * mask.z, p3 = e3 * inv * mask.w;
        avg.x += p0; avg.y += p1; avg.z += p2; avg.w += p3;

        __half2 lo = __floats2half2_rn(p0, p1);
        __half2 hi = __floats2half2_rn(p2, p3);
        *(uint2*)(g_p + roff + c) = make_uint2(h2u(lo), h2u(hi));
    }

    float* arow = avg_out + ((size_t)b * TGT + t) * SRC;
    float4 aw = { avg.x * (1.0f / NH), avg.y * (1.0f / NH),
                  avg.z * (1.0f / NH), avg.w * (1.0f / NH) };
    *(float4*)(arow + c) = aw;
}

// ---------------------------------------------------------------------------
extern "C" void kernel_launch(void* const* d_in, const int* in_sizes, int n_in,
                              void* d_out, int out_size)
{
    const float* query = (const float*)d_in[0];
    const float* key   = (const float*)d_in[1];
    const float* hard  = (const float*)d_in[2];
    const float* W     = (const float*)d_in[3];
    const float* bias  = (const float*)d_in[4];
    const float* Wo    = (const float*)d_in[5];
    const float* bo    = (const float*)d_in[6];
    float* out = (float*)d_out;
    float* avg_out = out + (size_t)TGT * BSZb * EMB;

    constexpr int SM_BIG = 2 * 128 * 128 + 2 * 128 * 128;   // 65536
    constexpr int SM_PV  = 2 * 128 * 128 + 2 * 64 * 128;    // 49152

    cudaFuncSetAttribute(hgemm<128, 128, 2, 4, 0>, cudaFuncAttributeMaxDynamicSharedMemorySize, SM_BIG);
    cudaFuncSetAttribute(hgemm<128, 128, 2, 4, 1>, cudaFuncAttributeMaxDynamicSharedMemorySize, SM_BIG);
    cudaFuncSetAttribute(hgemm<128, 128, 2, 4, 2>, cudaFuncAttributeMaxDynamicSharedMemorySize, SM_BIG);
    cudaFuncSetAttribute(hgemm<128, 128, 2, 4, 3>, cudaFuncAttributeMaxDynamicSharedMemorySize, SM_BIG);
    cudaFuncSetAttribute(hgemm<128, 64, 2, 4, 4>,  cudaFuncAttributeMaxDynamicSharedMemorySize, SM_PV);
    cudaFuncSetAttribute(hgemm<128, 128, 2, 4, 5>, cudaFuncAttributeMaxDynamicSharedMemorySize, SM_BIG);

    // 0: fp32 -> fp16 conversions
    {
        __half* p;
        int n4;
        cudaGetSymbolAddress((void**)&p, g_qin);
        n4 = TGT * BSZb * EMB / 4;
        cvt_kernel<<<(n4 + 255) / 256, 256>>>((const float4*)query, (uint2*)p, n4);
        cudaGetSymbolAddress((void**)&p, g_kin);
        cvt_kernel<<<(n4 + 255) / 256, 256>>>((const float4*)key, (uint2*)p, n4);
        cudaGetSymbolAddress((void**)&p, g_w16);
        n4 = 3 * EMB * EMB / 4;
        cvt_kernel<<<(n4 + 255) / 256, 256>>>((const float4*)W, (uint2*)p, n4);
        cudaGetSymbolAddress((void**)&p, g_wo16);
        n4 = EMB * EMB / 4;
        cvt_kernel<<<(n4 + 255) / 256, 256>>>((const float4*)Wo, (uint2*)p, n4);
    }

    // 1..3: QKV projections (M=4096, N=1024, K=1024)
    {
        dim3 grid(EMB / 128, TGT * BSZb / 128);
        hgemm<128, 128, 2, 4, 1><<<grid, 256, SM_BIG>>>(bias, nullptr, EMB, EMB, EMB);
        hgemm<128, 128, 2, 4, 2><<<grid, 256, SM_BIG>>>(bias + EMB, nullptr, EMB, EMB, EMB);
        hgemm<128, 128, 2, 4, 3><<<grid, 256, SM_BIG>>>(bias + 2 * EMB, nullptr, EMB, EMB, EMB);
    }
    // 4: scores = Q K^T per (b,h)  (K=64, single chunk)
    {
        dim3 grid(SRC / 128, TGT / 128, BSZb * NH);
        hgemm<128, 128, 2, 4, 0><<<grid, 256, SM_BIG>>>(nullptr, nullptr, HD, HD, HD);
    }
    // 5: softmax + mask + head-average
    {
        dim3 grid(TGT, BSZb);
        softmax_mask_avg_kernel<<<grid, 256>>>(hard, avg_out);
    }
    // 6: ctx = P V per (b,h)
    {
        dim3 grid(1, TGT / 128, BSZb * NH);
        hgemm<128, 64, 2, 4, 4><<<grid, 256, SM_PV>>>(nullptr, nullptr, SRC, SRC, HD);
    }
    // 7: out projection
    {
        dim3 grid(EMB / 128, TGT * BSZb / 128);
        hgemm<128, 128, 2, 4, 5><<<grid, 256, SM_BIG>>>(bo, out, EMB, EMB, EMB);
    }
}